// round 1
// baseline (speedup 1.0000x reference)
#include <cuda_runtime.h>
#include <cuda_bf16.h>

// Problem constants (fixed by the reference)
#define NB      2      // batch
#define NX      200
#define NY      200
#define NZ      16     // Z == HEIGHT, h = 1 -> height bin index == z
#define NC      17     // classes
#define NCHOOSE 4000
#define NHEIGHT 16
#define EMPTY_LAB 16
// MAX_W = 3, MIN_W/MAX_W = 1/3, log(1/3):
#define LOG_RATIO (-1.0986122886681098f)

// Persistent scratch (no allocations allowed)
__device__ int   g_counts[NB * NHEIGHT];
__device__ float g_weights[NB * NHEIGHT];
__device__ float g_sum[NB];
__device__ int   g_nval[NB];

// ---------------------------------------------------------------- init
__global__ void hv_init_k() {
    int t = threadIdx.x;
    if (t < NB * NHEIGHT) g_counts[t] = 0;
    if (t < NB) { g_sum[t] = 0.0f; g_nval[t] = 0; }
}

// ---------------------------------------------------------------- counts
// One thread per selected (b, s) column: reads 16 contiguous labels.
__global__ void hv_count_k(const int* __restrict__ labels,
                           const int* __restrict__ sel) {
    __shared__ int s_cnt[NB * NHEIGHT];
    if (threadIdx.x < NB * NHEIGHT) s_cnt[threadIdx.x] = 0;
    __syncthreads();

    int col = blockIdx.x * blockDim.x + threadIdx.x;
    if (col < NB * NCHOOSE) {
        int b = col / NCHOOSE;
        int x = sel[col * 2 + 0];
        int y = sel[col * 2 + 1];
        const int* lp = labels + (((b * NX + x) * NY) + y) * NZ;
        #pragma unroll
        for (int z = 0; z < NZ; ++z) {
            if (lp[z] != EMPTY_LAB) atomicAdd(&s_cnt[b * NHEIGHT + z], 1);
        }
    }
    __syncthreads();
    if (threadIdx.x < NB * NHEIGHT) {
        int c = s_cnt[threadIdx.x];
        if (c) atomicAdd(&g_counts[threadIdx.x], c);
    }
}

// ---------------------------------------------------------------- weights
// 32 threads: lane t -> (b = t/16, z = t%16). Max over each 16-lane half via
// shfl_xor (offsets 1,2,4,8 stay inside the half).
__global__ void hv_weights_k() {
    int t = threadIdx.x;
    float cnt = (float)g_counts[t];
    float mc = cnt;
    #pragma unroll
    for (int o = 1; o < 16; o <<= 1)
        mc = fmaxf(mc, __shfl_xor_sync(0xffffffffu, mc, o));
    mc = fmaxf(mc, 1.0f);
    g_weights[t] = (cnt > 0.0f) ? 3.0f * expf(LOG_RATIO * (cnt / mc)) : 0.0f;
}

// ---------------------------------------------------------------- loss
// One thread per (b, s, z) element. Consecutive 16 threads share one
// contiguous 1088-byte preds column -> good line reuse.
__global__ void hv_loss_k(const float* __restrict__ preds,
                          const int*   __restrict__ labels,
                          const int*   __restrict__ sel) {
    __shared__ float s_sum[NB];
    __shared__ int   s_n[NB];
    if (threadIdx.x < NB) { s_sum[threadIdx.x] = 0.0f; s_n[threadIdx.x] = 0; }
    __syncthreads();

    int e = blockIdx.x * blockDim.x + threadIdx.x;
    if (e < NB * NCHOOSE * NZ) {
        int z   = e & (NZ - 1);
        int col = e >> 4;
        int b   = col / NCHOOSE;
        int x   = sel[col * 2 + 0];
        int y   = sel[col * 2 + 1];
        int base = (((b * NX + x) * NY) + y) * NZ + z;   // voxel index
        int lab  = labels[base];
        if (lab != EMPTY_LAB) {
            const float* v = preds + (size_t)base * NC;
            float m = v[0];
            #pragma unroll
            for (int c = 1; c < NC; ++c) m = fmaxf(m, v[c]);
            float sum = 0.0f, pl = 0.0f;
            #pragma unroll
            for (int c = 0; c < NC; ++c) {
                float ex = expf(v[c] - m);
                sum += ex;
                if (c == lab) pl = ex;
            }
            float p  = pl / sum;
            float w  = g_weights[b * NHEIGHT + z];
            float wl = w * logf(p + 0.001f);
            float ax = fabsf(wl);
            float sl = (ax < 1.0f) ? 0.5f * wl * wl : (ax - 0.5f);
            atomicAdd(&s_sum[b], sl);
            atomicAdd(&s_n[b], 1);
        }
    }
    __syncthreads();
    if (threadIdx.x < NB) {
        if (s_n[threadIdx.x]) {
            atomicAdd(&g_sum[threadIdx.x],  s_sum[threadIdx.x]);
            atomicAdd(&g_nval[threadIdx.x], s_n[threadIdx.x]);
        }
    }
}

// ---------------------------------------------------------------- finalize
__global__ void hv_final_k(float* __restrict__ out) {
    float acc = 0.0f;
    #pragma unroll
    for (int b = 0; b < NB; ++b)
        acc += g_sum[b] / fmaxf((float)g_nval[b], 1.0f);
    out[0] = acc / (float)NB;
}

// ---------------------------------------------------------------- launch
extern "C" void kernel_launch(void* const* d_in, const int* in_sizes, int n_in,
                              void* d_out, int out_size) {
    const float* preds  = (const float*)d_in[0];
    const int*   labels = (const int*)  d_in[1];
    const int*   sel    = (const int*)  d_in[2];
    float* out = (float*)d_out;

    hv_init_k<<<1, 64>>>();

    {
        int n = NB * NCHOOSE;                 // 8000 columns
        int threads = 256;
        int blocks  = (n + threads - 1) / threads;
        hv_count_k<<<blocks, threads>>>(labels, sel);
    }

    hv_weights_k<<<1, 32>>>();

    {
        int n = NB * NCHOOSE * NZ;            // 128000 elements
        int threads = 256;
        int blocks  = (n + threads - 1) / threads;
        hv_loss_k<<<blocks, threads>>>(preds, labels, sel);
    }

    hv_final_k<<<1, 1>>>(out);
}